// round 5
// baseline (speedup 1.0000x reference)
#include <cuda_runtime.h>

#define NN 20000
#define TT 20
#define FF 128
#define HH 128
#define EE 640000
#define EL (EE + NN)
#define NHEADS 4
#define NTT (NN * TT)

// ------------------------------------------------------------------
// Static device scratch (no runtime allocations allowed)
// ------------------------------------------------------------------
__device__ float g_Wih[FF * 1024];          // [k][j], j = dir*512 + gate*128 + u
__device__ float g_bih[1024];
__device__ float g_Whh[2][HH][512];         // [dir][k][gate*128+u]
__device__ float g_W1t[256 * 512];          // [k][j]
__device__ float g_W2t[512 * 128];          // [k][j]
__device__ float g_pre[(size_t)NTT * 1024]; // sorted-row space: (i*T+t)*1024 + j
__device__ float g_gates[(size_t)NN * 1024];
__device__ float g_h[2][NN][HH];            // sorted space
__device__ float g_c[2][NN][HH];
__device__ float g_hcat[(size_t)NN * 256];  // original node order
__device__ float g_xh1[(size_t)NN * 512];
__device__ float g_h1[(size_t)NN * 512];
__device__ float g_xh2[(size_t)NN * 128];
__device__ float g_h2[(size_t)NN * 128];
__device__ float g_als1[NN * NHEADS];
__device__ float g_ald1[NN * NHEADS];
__device__ float g_als2[NN];
__device__ float g_ald2[NN];
// length sort
__device__ int g_cnt[21];
__device__ int g_lcur[21];
__device__ int g_active[TT];
__device__ int g_perm[NN];
__device__ int g_lenp[NN];
__device__ int g_nrows;
__device__ int g_rowA[NTT]; // source row in x
__device__ int g_rowC[NTT]; // dest row in g_pre (sorted space)
// CSR by dst
__device__ int g_deg[NN];
__device__ int g_rowptr[NN + 1];
__device__ int g_cursor[NN];
__device__ int g_csrc[EL];

// ------------------------------------------------------------------
// init / prep
// ------------------------------------------------------------------
__global__ void k_zero() {
    int i0 = blockIdx.x * blockDim.x + threadIdx.x;
    int stride = gridDim.x * blockDim.x;
    float* h = &g_h[0][0][0];
    float* c = &g_c[0][0][0];
    const int nh = 2 * NN * HH;
    for (int i = i0; i < nh; i += stride) { h[i] = 0.f; c[i] = 0.f; }
    for (int i = i0; i < NN; i += stride) g_deg[i] = 0;
    if (i0 < 21) g_cnt[i0] = 0;
    if (i0 == 0) g_nrows = 0;
}

__global__ void k_prep(const float* __restrict__ Wih_f, const float* __restrict__ Whh_f,
                       const float* __restrict__ b_f,
                       const float* __restrict__ Wih_b, const float* __restrict__ Whh_b,
                       const float* __restrict__ b_b,
                       const float* __restrict__ W1, const float* __restrict__ W2) {
    int idx = blockIdx.x * blockDim.x + threadIdx.x;
    if (idx < 131072) {                        // Wih: k in [0,128), j in [0,1024)
        int k = idx >> 10, j = idx & 1023;
        int d = j >> 9, jj = j & 511;
        const float* W = d ? Wih_b : Wih_f;    // [512,128] row-major
        g_Wih[idx] = W[jj * FF + k];
    } else if (idx < 262144) {                 // Whh: 2 dirs x 128 x 512
        int r = idx - 131072;
        int d = r >> 16;
        int rr = r & 65535;
        int k = rr >> 9, j = rr & 511;
        const float* W = d ? Whh_b : Whh_f;    // [512,128]
        g_Whh[d][k][j] = W[j * HH + k];
    } else if (idx < 393216) {                 // W1t: [256][512]
        int r = idx - 262144;
        int k = r >> 9, j = r & 511;
        g_W1t[r] = W1[j * 256 + k];            // W1: [512,256]
    } else if (idx < 458752) {                 // W2t: [512][128]
        int r = idx - 393216;
        int k = r >> 7, j = r & 127;
        g_W2t[r] = W2[j * 512 + k];            // W2: [128,512]
    } else if (idx < 459776) {                 // bias
        int j = idx - 458752;
        int d = j >> 9, jj = j & 511;
        g_bih[j] = (d ? b_b : b_f)[jj];
    }
}

// ------------------------------------------------------------------
// length counting-sort (descending) + compacted valid-row list
// ------------------------------------------------------------------
__global__ void k_hist(const int* __restrict__ lengths) {
    int n = blockIdx.x * blockDim.x + threadIdx.x;
    if (n < NN) atomicAdd(&g_cnt[lengths[n]], 1);
}

__global__ void k_prepL() {
    int suf = 0;
    for (int l = 20; l >= 0; l--) {
        g_lcur[l] = suf;                 // start offset of length-l group (desc order)
        if (l < TT) g_active[l] = suf;   // #{len > l}
        suf += g_cnt[l];
    }
}

__global__ void k_scatterL(const int* __restrict__ lengths) {
    int n = blockIdx.x * blockDim.x + threadIdx.x;
    if (n < NN) {
        int l = lengths[n];
        int i = atomicAdd(&g_lcur[l], 1);
        g_perm[i] = n;
        g_lenp[i] = l;
    }
}

__global__ void k_rows() {
    int idx = blockIdx.x * blockDim.x + threadIdx.x;
    if (idx < NTT) {
        int i = idx / TT, t = idx % TT;
        if (t < g_lenp[i]) {
            int p = atomicAdd(&g_nrows, 1);
            g_rowA[p] = g_perm[i] * TT + t;
            g_rowC[p] = idx;
        }
    }
}

// ------------------------------------------------------------------
// shared SGEMM body: 128x128 tile, K-chunks of 8, 256 threads, 8x8 acc
// ------------------------------------------------------------------
__device__ __forceinline__ void sgemm_loop(const float* __restrict__ Aptr,
                                           const float* __restrict__ Bbase, int ldb, int bcol,
                                           int K, int tid, float acc[8][8],
                                           float (*As)[132], float (*Bs)[132]) {
    int ar = tid >> 1;
    int ak = (tid & 1) * 4;
    int bk = tid >> 5;
    int bj = (tid & 31) * 4;
    int ty = tid >> 4, tx = tid & 15;
    for (int k0 = 0; k0 < K; k0 += 8) {
        float4 av = *(const float4*)(Aptr + k0 + ak);
        float4 bv = *(const float4*)(Bbase + (size_t)(k0 + bk) * ldb + bcol + bj);
        As[ak + 0][ar] = av.x; As[ak + 1][ar] = av.y;
        As[ak + 2][ar] = av.z; As[ak + 3][ar] = av.w;
        *(float4*)&Bs[bk][bj] = bv;
        __syncthreads();
#pragma unroll
        for (int kk = 0; kk < 8; kk++) {
            float a[8], b[8];
#pragma unroll
            for (int q = 0; q < 8; q++) a[q] = As[kk][ty * 8 + q];
#pragma unroll
            for (int q = 0; q < 8; q++) b[q] = Bs[kk][tx * 8 + q];
#pragma unroll
            for (int ii = 0; ii < 8; ii++)
#pragma unroll
                for (int jj = 0; jj < 8; jj++)
                    acc[ii][jj] = fmaf(a[ii], b[jj], acc[ii][jj]);
        }
        __syncthreads();
    }
}

// pre-gates: gathered x rows -> g_pre (+bias), compacted valid rows only
__global__ __launch_bounds__(256) void k_gemm_pre(const float* __restrict__ x) {
    __shared__ float As[8][132], Bs[8][132];
    int nr = g_nrows;
    int row0 = blockIdx.x * 128;
    if (row0 >= nr) return;
    int col0 = blockIdx.y * 128;
    int tid = threadIdx.x;
    int agr = row0 + (tid >> 1);
    if (agr > nr - 1) agr = nr - 1;
    const float* Aptr = x + (size_t)g_rowA[agr] * FF;
    float acc[8][8];
#pragma unroll
    for (int i = 0; i < 8; i++)
#pragma unroll
        for (int j = 0; j < 8; j++) acc[i][j] = 0.f;
    sgemm_loop(Aptr, g_Wih, 1024, col0, 128, tid, acc, As, Bs);
    int ty = tid >> 4, tx = tid & 15;
    float bb[8];
#pragma unroll
    for (int jj = 0; jj < 8; jj++) bb[jj] = g_bih[col0 + tx * 8 + jj];
#pragma unroll
    for (int ii = 0; ii < 8; ii++) {
        int r = row0 + ty * 8 + ii;
        if (r < nr) {
            float* Cp = g_pre + (size_t)g_rowC[r] * 1024 + col0 + tx * 8;
#pragma unroll
            for (int jj = 0; jj < 8; jj++) Cp[jj] = acc[ii][jj] + bb[jj];
        }
    }
}

// recurrence GEMM: gates = pre + h @ Whh^T, active-prefix rows only
__global__ __launch_bounds__(256) void k_gemm_rec(int t) {
    __shared__ float As[8][132], Bs[8][132];
    int nact = g_active[t];
    int row0 = blockIdx.x * 128;
    if (row0 >= nact) return;
    int col0 = blockIdx.y * 128;
    int d = col0 >> 9;
    int jloc = col0 & 511;
    int tid = threadIdx.x;
    int arow = row0 + (tid >> 1);
    if (arow > NN - 1) arow = NN - 1;
    const float* Aptr = &g_h[d][arow][0];
    float acc[8][8];
#pragma unroll
    for (int i = 0; i < 8; i++)
#pragma unroll
        for (int j = 0; j < 8; j++) acc[i][j] = 0.f;
    sgemm_loop(Aptr, &g_Whh[d][0][0], 512, jloc, 128, tid, acc, As, Bs);
    int ty = tid >> 4, tx = tid & 15;
#pragma unroll
    for (int ii = 0; ii < 8; ii++) {
        int r = row0 + ty * 8 + ii;
        if (r < nact) {
            int prow = (d == 0) ? (r * TT + t) : (r * TT + (g_lenp[r] - 1 - t));
            const float* Pp = g_pre + (size_t)prow * 1024 + col0 + tx * 8;
            float* Cp = g_gates + (size_t)r * 1024 + col0 + tx * 8;
#pragma unroll
            for (int jj = 0; jj < 8; jj++) Cp[jj] = acc[ii][jj] + Pp[jj];
        }
    }
}

__global__ void k_cell(int t) {
    int i = blockIdx.x;
    if (i >= g_active[t]) return;
    int tid = threadIdx.x;
    int d = tid >> 7, u = tid & 127;
    size_t base = (size_t)i * 1024 + d * 512;
    float iv = g_gates[base + u];
    float fv = g_gates[base + 128 + u];
    float gv = g_gates[base + 256 + u];
    float ov = g_gates[base + 384 + u];
    float si = 1.f / (1.f + expf(-iv));
    float sf = 1.f / (1.f + expf(-fv));
    float so = 1.f / (1.f + expf(-ov));
    float cn = sf * g_c[d][i][u] + si * tanhf(gv);
    g_c[d][i][u] = cn;
    g_h[d][i][u] = so * tanhf(cn);
}

__global__ void k_hcat() {
    int gid = blockIdx.x * blockDim.x + threadIdx.x;
    if (gid >= NN * HH) return;
    int i = gid >> 7, u = gid & 127;
    int n = g_perm[i];
    g_hcat[(size_t)n * 256 + u] = g_h[0][i][u];
    g_hcat[(size_t)n * 256 + 128 + u] = g_h[1][i][u];
}

// GAT projection GEMMs
__global__ __launch_bounds__(256) void k_gemm_xh1() {
    __shared__ float As[8][132], Bs[8][132];
    int row0 = blockIdx.x * 128;
    if (row0 >= NN) return;
    int col0 = blockIdx.y * 128;
    int tid = threadIdx.x;
    int arow = row0 + (tid >> 1);
    if (arow > NN - 1) arow = NN - 1;
    const float* Aptr = g_hcat + (size_t)arow * 256;
    float acc[8][8];
#pragma unroll
    for (int i = 0; i < 8; i++)
#pragma unroll
        for (int j = 0; j < 8; j++) acc[i][j] = 0.f;
    sgemm_loop(Aptr, g_W1t, 512, col0, 256, tid, acc, As, Bs);
    int ty = tid >> 4, tx = tid & 15;
#pragma unroll
    for (int ii = 0; ii < 8; ii++) {
        int r = row0 + ty * 8 + ii;
        if (r < NN) {
            float* Cp = g_xh1 + (size_t)r * 512 + col0 + tx * 8;
#pragma unroll
            for (int jj = 0; jj < 8; jj++) Cp[jj] = acc[ii][jj];
        }
    }
}

__global__ __launch_bounds__(256) void k_gemm_xh2() {
    __shared__ float As[8][132], Bs[8][132];
    int row0 = blockIdx.x * 128;
    if (row0 >= NN) return;
    int tid = threadIdx.x;
    int arow = row0 + (tid >> 1);
    if (arow > NN - 1) arow = NN - 1;
    const float* Aptr = g_h1 + (size_t)arow * 512;
    float acc[8][8];
#pragma unroll
    for (int i = 0; i < 8; i++)
#pragma unroll
        for (int j = 0; j < 8; j++) acc[i][j] = 0.f;
    sgemm_loop(Aptr, g_W2t, 128, 0, 512, tid, acc, As, Bs);
    int ty = tid >> 4, tx = tid & 15;
#pragma unroll
    for (int ii = 0; ii < 8; ii++) {
        int r = row0 + ty * 8 + ii;
        if (r < NN) {
            float* Cp = g_xh2 + (size_t)r * 128 + tx * 8;
#pragma unroll
            for (int jj = 0; jj < 8; jj++) Cp[jj] = acc[ii][jj];
        }
    }
}

// attention logits
__global__ void k_al1(const float* __restrict__ a1s, const float* __restrict__ a1d) {
    int wid = (blockIdx.x * blockDim.x + threadIdx.x) >> 5;
    int lane = threadIdx.x & 31;
    if (wid >= NN * NHEADS) return;
    int n = wid >> 2, h = wid & 3;
    float s1 = 0.f, s2 = 0.f;
#pragma unroll
    for (int q = 0; q < 4; q++) {
        int f = h * 128 + lane + q * 32;
        float xv = g_xh1[(size_t)n * 512 + f];
        s1 = fmaf(xv, a1s[f], s1);
        s2 = fmaf(xv, a1d[f], s2);
    }
#pragma unroll
    for (int o = 16; o; o >>= 1) {
        s1 += __shfl_xor_sync(0xffffffffu, s1, o);
        s2 += __shfl_xor_sync(0xffffffffu, s2, o);
    }
    if (lane == 0) { g_als1[n * 4 + h] = s1; g_ald1[n * 4 + h] = s2; }
}

__global__ void k_al2(const float* __restrict__ a2s, const float* __restrict__ a2d) {
    int wid = (blockIdx.x * blockDim.x + threadIdx.x) >> 5;
    int lane = threadIdx.x & 31;
    if (wid >= NN) return;
    int n = wid;
    float s1 = 0.f, s2 = 0.f;
#pragma unroll
    for (int q = 0; q < 4; q++) {
        int f = lane + q * 32;
        float xv = g_xh2[(size_t)n * 128 + f];
        s1 = fmaf(xv, a2s[f], s1);
        s2 = fmaf(xv, a2d[f], s2);
    }
#pragma unroll
    for (int o = 16; o; o >>= 1) {
        s1 += __shfl_xor_sync(0xffffffffu, s1, o);
        s2 += __shfl_xor_sync(0xffffffffu, s2, o);
    }
    if (lane == 0) { g_als2[n] = s1; g_ald2[n] = s2; }
}

// ------------------------------------------------------------------
// CSR by destination (edges + self loops)
// ------------------------------------------------------------------
__global__ void k_deg(const int* __restrict__ ei) {
    int i = blockIdx.x * blockDim.x + threadIdx.x;
    if (i < EL) {
        int dst = (i < EE) ? ei[EE + i] : (i - EE);
        atomicAdd(&g_deg[dst], 1);
    }
}

__global__ void k_scan() {
    __shared__ int s[1024];
    const int C = 20;
    int tt = threadIdx.x;
    int begin = tt * C;
    int sum = 0;
    for (int i = 0; i < C; i++) {
        int idx = begin + i;
        if (idx < NN) sum += g_deg[idx];
    }
    s[tt] = sum;
    __syncthreads();
    for (int off = 1; off < 1024; off <<= 1) {
        int v = 0;
        if (tt >= off) v = s[tt - off];
        __syncthreads();
        if (tt >= off) s[tt] += v;
        __syncthreads();
    }
    int excl = s[tt] - sum;
    for (int i = 0; i < C; i++) {
        int idx = begin + i;
        if (idx < NN) { g_rowptr[idx] = excl; excl += g_deg[idx]; }
    }
    if (tt == 1023) g_rowptr[NN] = s[1023];
}

__global__ void k_cursor() {
    int i = blockIdx.x * blockDim.x + threadIdx.x;
    if (i < NN) g_cursor[i] = g_rowptr[i];
}

__global__ void k_scat_e(const int* __restrict__ ei) {
    int i = blockIdx.x * blockDim.x + threadIdx.x;
    if (i < EL) {
        int src = (i < EE) ? ei[i] : (i - EE);
        int dst = (i < EE) ? ei[EE + i] : (i - EE);
        int pos = atomicAdd(&g_cursor[dst], 1);
        g_csrc[pos] = src;
    }
}

// ------------------------------------------------------------------
// GAT aggregation (softmax by dst) — warp per (node, head)
// ------------------------------------------------------------------
__global__ __launch_bounds__(128) void k_gat1_agg(const float* __restrict__ bias1) {
    int n = blockIdx.x;
    int w = threadIdx.x >> 5;   // head
    int lane = threadIdx.x & 31;
    float aldn = g_ald1[n * 4 + w];
    int start = g_rowptr[n], end = g_rowptr[n + 1];
    float emax = -1e30f;
    for (int j = start + lane; j < end; j += 32) {
        int s = g_csrc[j];
        float v = g_als1[s * 4 + w] + aldn;
        v = v > 0.f ? v : 0.2f * v;
        emax = fmaxf(emax, v);
    }
#pragma unroll
    for (int o = 16; o; o >>= 1) emax = fmaxf(emax, __shfl_xor_sync(0xffffffffu, emax, o));
    float denom = 0.f, a0 = 0.f, a1 = 0.f, a2 = 0.f, a3 = 0.f;
    for (int j = start; j < end; j++) {
        int s = g_csrc[j];
        float v = g_als1[s * 4 + w] + aldn;
        v = v > 0.f ? v : 0.2f * v;
        float we = expf(v - emax);
        denom += we;
        const float* xb = g_xh1 + (size_t)s * 512 + w * 128 + lane;
        a0 = fmaf(we, xb[0], a0);
        a1 = fmaf(we, xb[32], a1);
        a2 = fmaf(we, xb[64], a2);
        a3 = fmaf(we, xb[96], a3);
    }
    float inv = 1.f / (denom + 1e-16f);
    int ob = n * 512 + w * 128 + lane;
    int fb = w * 128 + lane;
    g_h1[ob]      = fmaxf(fmaf(a0, inv, 0.f) + bias1[fb], 0.f);
    g_h1[ob + 32] = fmaxf(a1 * inv + bias1[fb + 32], 0.f);
    g_h1[ob + 64] = fmaxf(a2 * inv + bias1[fb + 64], 0.f);
    g_h1[ob + 96] = fmaxf(a3 * inv + bias1[fb + 96], 0.f);
}

__global__ void k_gat2_agg(const float* __restrict__ bias2) {
    int wid = (blockIdx.x * blockDim.x + threadIdx.x) >> 5;
    if (wid >= NN) return;
    int lane = threadIdx.x & 31;
    int n = wid;
    float aldn = g_ald2[n];
    int start = g_rowptr[n], end = g_rowptr[n + 1];
    float emax = -1e30f;
    for (int j = start + lane; j < end; j += 32) {
        int s = g_csrc[j];
        float v = g_als2[s] + aldn;
        v = v > 0.f ? v : 0.2f * v;
        emax = fmaxf(emax, v);
    }
#pragma unroll
    for (int o = 16; o; o >>= 1) emax = fmaxf(emax, __shfl_xor_sync(0xffffffffu, emax, o));
    float denom = 0.f, a0 = 0.f, a1 = 0.f, a2 = 0.f, a3 = 0.f;
    for (int j = start; j < end; j++) {
        int s = g_csrc[j];
        float v = g_als2[s] + aldn;
        v = v > 0.f ? v : 0.2f * v;
        float we = expf(v - emax);
        denom += we;
        const float* xb = g_xh2 + (size_t)s * 128 + lane;
        a0 = fmaf(we, xb[0], a0);
        a1 = fmaf(we, xb[32], a1);
        a2 = fmaf(we, xb[64], a2);
        a3 = fmaf(we, xb[96], a3);
    }
    float inv = 1.f / (denom + 1e-16f);
    int ob = n * 128 + lane;
    g_h2[ob]      = fmaxf(a0 * inv + bias2[lane], 0.f);
    g_h2[ob + 32] = fmaxf(a1 * inv + bias2[lane + 32], 0.f);
    g_h2[ob + 64] = fmaxf(a2 * inv + bias2[lane + 64], 0.f);
    g_h2[ob + 96] = fmaxf(a3 * inv + bias2[lane + 96], 0.f);
}

// final FC — warp per node
__global__ void k_fc(const float* __restrict__ Wfc, const float* __restrict__ bfc,
                     float* __restrict__ out) {
    int wid = (blockIdx.x * blockDim.x + threadIdx.x) >> 5;
    if (wid >= NN) return;
    int lane = threadIdx.x & 31;
    int n = wid;
    float hv[4];
#pragma unroll
    for (int q = 0; q < 4; q++) hv[q] = g_h2[(size_t)n * 128 + lane + 32 * q];
#pragma unroll
    for (int c = 0; c < 10; c++) {
        float p = 0.f;
#pragma unroll
        for (int q = 0; q < 4; q++) p = fmaf(hv[q], Wfc[c * 128 + lane + 32 * q], p);
#pragma unroll
        for (int o = 16; o; o >>= 1) p += __shfl_xor_sync(0xffffffffu, p, o);
        if (lane == 0) out[n * 10 + c] = p + bfc[c];
    }
}

// ------------------------------------------------------------------
extern "C" void kernel_launch(void* const* d_in, const int* in_sizes, int n_in,
                              void* d_out, int out_size) {
    (void)in_sizes; (void)n_in; (void)out_size;
    const float* x        = (const float*)d_in[0];
    const int*   lengths  = (const int*)d_in[1];
    const int*   ei       = (const int*)d_in[2];
    const float* Wih_f    = (const float*)d_in[3];
    const float* Whh_f    = (const float*)d_in[4];
    const float* b_f      = (const float*)d_in[5];
    const float* Wih_b    = (const float*)d_in[6];
    const float* Whh_b    = (const float*)d_in[7];
    const float* b_b      = (const float*)d_in[8];
    const float* W1       = (const float*)d_in[9];
    const float* a1_src   = (const float*)d_in[10];
    const float* a1_dst   = (const float*)d_in[11];
    const float* bias1    = (const float*)d_in[12];
    const float* W2       = (const float*)d_in[13];
    const float* a2_src   = (const float*)d_in[14];
    const float* a2_dst   = (const float*)d_in[15];
    const float* bias2    = (const float*)d_in[16];
    const float* Wfc      = (const float*)d_in[17];
    const float* bfc      = (const float*)d_in[18];
    float* out = (float*)d_out;

    k_zero<<<1024, 256>>>();
    k_prep<<<(459776 + 255) / 256, 256>>>(Wih_f, Whh_f, b_f, Wih_b, Whh_b, b_b, W1, W2);
    k_hist<<<(NN + 255) / 256, 256>>>(lengths);
    k_prepL<<<1, 1>>>();
    k_scatterL<<<(NN + 255) / 256, 256>>>(lengths);
    k_rows<<<(NTT + 255) / 256, 256>>>();

    // CSR build (independent of LSTM)
    k_deg<<<(EL + 255) / 256, 256>>>(ei);
    k_scan<<<1, 1024>>>();
    k_cursor<<<(NN + 255) / 256, 256>>>();
    k_scat_e<<<(EL + 255) / 256, 256>>>(ei);

    // input projection over compacted valid rows
    k_gemm_pre<<<dim3((NTT + 127) / 128, 8), 256>>>(x);

    // recurrence
    for (int t = 0; t < TT; t++) {
        k_gemm_rec<<<dim3((NN + 127) / 128, 8), 256>>>(t);
        k_cell<<<NN, 256>>>(t);
    }
    k_hcat<<<(NN * HH + 255) / 256, 256>>>();

    // GAT layer 1
    k_gemm_xh1<<<dim3((NN + 127) / 128, 4), 256>>>();
    k_al1<<<(NN * NHEADS * 32 + 255) / 256, 256>>>(a1_src, a1_dst);
    k_gat1_agg<<<NN, 128>>>(bias1);

    // GAT layer 2
    k_gemm_xh2<<<dim3((NN + 127) / 128, 1), 256>>>();
    k_al2<<<(NN * 32 + 255) / 256, 256>>>(a2_src, a2_dst);
    k_gat2_agg<<<(NN * 32 + 255) / 256, 256>>>(bias2);

    // FC
    k_fc<<<(NN * 32 + 255) / 256, 256>>>(Wfc, bfc, out);
}

// round 9
// speedup vs baseline: 1.0056x; 1.0056x over previous
#include <cuda_runtime.h>

#define NN 20000
#define TT 20
#define FF 128
#define HH 128
#define EE 640000
#define EL (EE + NN)
#define NHEADS 4
#define NTT (NN * TT)

// ------------------------------------------------------------------
// Static device scratch (no runtime allocations allowed)
// ------------------------------------------------------------------
__device__ float g_Wih[FF * 1024];          // [k][j], j = dir*512 + gate*128 + u
__device__ float g_bih[1024];
__device__ float g_Whh[2][HH][512];         // [dir][k][gate*128+u]
__device__ float g_W1t[256 * 512];          // [k][j]
__device__ float g_W2t[512 * 128];          // [k][j]
__device__ float g_pre[(size_t)NTT * 1024]; // sorted-row space: (i*T+t)*1024 + j
__device__ float g_gates[(size_t)NN * 1024];
__device__ float g_h[2][NN][HH];            // sorted space
__device__ float g_c[2][NN][HH];
__device__ float g_hcat[(size_t)NN * 256];  // original node order
__device__ float g_xh1[(size_t)NN * 512];
__device__ float g_h1[(size_t)NN * 512];
__device__ float g_xh2[(size_t)NN * 128];
__device__ float g_h2[(size_t)NN * 128];
__device__ float g_als1[NN * NHEADS];
__device__ float g_ald1[NN * NHEADS];
__device__ float g_als2[NN];
__device__ float g_ald2[NN];
// length sort
__device__ int g_cnt[21];
__device__ int g_lcur[21];
__device__ int g_active[TT];
__device__ int g_perm[NN];
__device__ int g_lenp[NN];
__device__ int g_nrows;
__device__ int g_rowA[NTT]; // source row in x
__device__ int g_rowC[NTT]; // dest row in g_pre (sorted space)
// CSR by dst
__device__ int g_deg[NN];
__device__ int g_rowptr[NN + 1];
__device__ int g_cursor[NN];
__device__ int g_csrc[EL];

// ------------------------------------------------------------------
// init / prep
// ------------------------------------------------------------------
__global__ void k_zero() {
    int i0 = blockIdx.x * blockDim.x + threadIdx.x;
    int stride = gridDim.x * blockDim.x;
    float* h = &g_h[0][0][0];
    float* c = &g_c[0][0][0];
    const int nh = 2 * NN * HH;
    for (int i = i0; i < nh; i += stride) { h[i] = 0.f; c[i] = 0.f; }
    for (int i = i0; i < NN; i += stride) g_deg[i] = 0;
    if (i0 < 21) g_cnt[i0] = 0;
    if (i0 == 0) g_nrows = 0;
}

__global__ void k_prep(const float* __restrict__ Wih_f, const float* __restrict__ Whh_f,
                       const float* __restrict__ b_f,
                       const float* __restrict__ Wih_b, const float* __restrict__ Whh_b,
                       const float* __restrict__ b_b,
                       const float* __restrict__ W1, const float* __restrict__ W2) {
    int idx = blockIdx.x * blockDim.x + threadIdx.x;
    if (idx < 131072) {                        // Wih: k in [0,128), j in [0,1024)
        int k = idx >> 10, j = idx & 1023;
        int d = j >> 9, jj = j & 511;
        const float* W = d ? Wih_b : Wih_f;    // [512,128] row-major
        g_Wih[idx] = W[jj * FF + k];
    } else if (idx < 262144) {                 // Whh: 2 dirs x 128 x 512
        int r = idx - 131072;
        int d = r >> 16;
        int rr = r & 65535;
        int k = rr >> 9, j = rr & 511;
        const float* W = d ? Whh_b : Whh_f;    // [512,128]
        g_Whh[d][k][j] = W[j * HH + k];
    } else if (idx < 393216) {                 // W1t: [256][512]
        int r = idx - 262144;
        int k = r >> 9, j = r & 511;
        g_W1t[r] = W1[j * 256 + k];            // W1: [512,256]
    } else if (idx < 458752) {                 // W2t: [512][128]
        int r = idx - 393216;
        int k = r >> 7, j = r & 127;
        g_W2t[r] = W2[j * 512 + k];            // W2: [128,512]
    } else if (idx < 459776) {                 // bias
        int j = idx - 458752;
        int d = j >> 9, jj = j & 511;
        g_bih[j] = (d ? b_b : b_f)[jj];
    }
}

// ------------------------------------------------------------------
// length counting-sort (descending) + compacted valid-row list
// ------------------------------------------------------------------
__global__ void k_hist(const int* __restrict__ lengths) {
    int n = blockIdx.x * blockDim.x + threadIdx.x;
    if (n < NN) atomicAdd(&g_cnt[lengths[n]], 1);
}

__global__ void k_prepL() {
    int suf = 0;
    for (int l = 20; l >= 0; l--) {
        g_lcur[l] = suf;                 // start offset of length-l group (desc order)
        if (l < TT) g_active[l] = suf;   // #{len > l}
        suf += g_cnt[l];
    }
}

__global__ void k_scatterL(const int* __restrict__ lengths) {
    int n = blockIdx.x * blockDim.x + threadIdx.x;
    if (n < NN) {
        int l = lengths[n];
        int i = atomicAdd(&g_lcur[l], 1);
        g_perm[i] = n;
        g_lenp[i] = l;
    }
}

__global__ void k_rows() {
    int idx = blockIdx.x * blockDim.x + threadIdx.x;
    if (idx < NTT) {
        int i = idx / TT, t = idx % TT;
        if (t < g_lenp[i]) {
            int p = atomicAdd(&g_nrows, 1);
            g_rowA[p] = g_perm[i] * TT + t;
            g_rowC[p] = idx;
        }
    }
}

// ------------------------------------------------------------------
// shared SGEMM body: 128x128 tile, K-chunks of 8, 256 threads, 8x8 acc
// ------------------------------------------------------------------
__device__ __forceinline__ void sgemm_loop(const float* __restrict__ Aptr,
                                           const float* __restrict__ Bbase, int ldb, int bcol,
                                           int K, int tid, float acc[8][8],
                                           float (*As)[132], float (*Bs)[132]) {
    int ar = tid >> 1;
    int ak = (tid & 1) * 4;
    int bk = tid >> 5;
    int bj = (tid & 31) * 4;
    int ty = tid >> 4, tx = tid & 15;
    for (int k0 = 0; k0 < K; k0 += 8) {
        float4 av = *(const float4*)(Aptr + k0 + ak);
        float4 bv = *(const float4*)(Bbase + (size_t)(k0 + bk) * ldb + bcol + bj);
        As[ak + 0][ar] = av.x; As[ak + 1][ar] = av.y;
        As[ak + 2][ar] = av.z; As[ak + 3][ar] = av.w;
        *(float4*)&Bs[bk][bj] = bv;
        __syncthreads();
#pragma unroll
        for (int kk = 0; kk < 8; kk++) {
            float a[8], b[8];
#pragma unroll
            for (int q = 0; q < 8; q++) a[q] = As[kk][ty * 8 + q];
#pragma unroll
            for (int q = 0; q < 8; q++) b[q] = Bs[kk][tx * 8 + q];
#pragma unroll
            for (int ii = 0; ii < 8; ii++)
#pragma unroll
                for (int jj = 0; jj < 8; jj++)
                    acc[ii][jj] = fmaf(a[ii], b[jj], acc[ii][jj]);
        }
        __syncthreads();
    }
}

// pre-gates: gathered x rows -> g_pre (+bias), compacted valid rows only
__global__ __launch_bounds__(256) void k_gemm_pre(const float* __restrict__ x) {
    __shared__ float As[8][132], Bs[8][132];
    int nr = g_nrows;
    int row0 = blockIdx.x * 128;
    if (row0 >= nr) return;
    int col0 = blockIdx.y * 128;
    int tid = threadIdx.x;
    int agr = row0 + (tid >> 1);
    if (agr > nr - 1) agr = nr - 1;
    const float* Aptr = x + (size_t)g_rowA[agr] * FF;
    float acc[8][8];
#pragma unroll
    for (int i = 0; i < 8; i++)
#pragma unroll
        for (int j = 0; j < 8; j++) acc[i][j] = 0.f;
    sgemm_loop(Aptr, g_Wih, 1024, col0, 128, tid, acc, As, Bs);
    int ty = tid >> 4, tx = tid & 15;
    float bb[8];
#pragma unroll
    for (int jj = 0; jj < 8; jj++) bb[jj] = g_bih[col0 + tx * 8 + jj];
#pragma unroll
    for (int ii = 0; ii < 8; ii++) {
        int r = row0 + ty * 8 + ii;
        if (r < nr) {
            float* Cp = g_pre + (size_t)g_rowC[r] * 1024 + col0 + tx * 8;
#pragma unroll
            for (int jj = 0; jj < 8; jj++) Cp[jj] = acc[ii][jj] + bb[jj];
        }
    }
}

// recurrence GEMM: gates = pre + h @ Whh^T, active-prefix rows only
__global__ __launch_bounds__(256) void k_gemm_rec(int t) {
    __shared__ float As[8][132], Bs[8][132];
    int nact = g_active[t];
    int row0 = blockIdx.x * 128;
    if (row0 >= nact) return;
    int col0 = blockIdx.y * 128;
    int d = col0 >> 9;
    int jloc = col0 & 511;
    int tid = threadIdx.x;
    int arow = row0 + (tid >> 1);
    if (arow > NN - 1) arow = NN - 1;
    const float* Aptr = &g_h[d][arow][0];
    float acc[8][8];
#pragma unroll
    for (int i = 0; i < 8; i++)
#pragma unroll
        for (int j = 0; j < 8; j++) acc[i][j] = 0.f;
    sgemm_loop(Aptr, &g_Whh[d][0][0], 512, jloc, 128, tid, acc, As, Bs);
    int ty = tid >> 4, tx = tid & 15;
#pragma unroll
    for (int ii = 0; ii < 8; ii++) {
        int r = row0 + ty * 8 + ii;
        if (r < nact) {
            int prow = (d == 0) ? (r * TT + t) : (r * TT + (g_lenp[r] - 1 - t));
            const float* Pp = g_pre + (size_t)prow * 1024 + col0 + tx * 8;
            float* Cp = g_gates + (size_t)r * 1024 + col0 + tx * 8;
#pragma unroll
            for (int jj = 0; jj < 8; jj++) Cp[jj] = acc[ii][jj] + Pp[jj];
        }
    }
}

__global__ void k_cell(int t) {
    int i = blockIdx.x;
    if (i >= g_active[t]) return;
    int tid = threadIdx.x;
    int d = tid >> 7, u = tid & 127;
    size_t base = (size_t)i * 1024 + d * 512;
    float iv = g_gates[base + u];
    float fv = g_gates[base + 128 + u];
    float gv = g_gates[base + 256 + u];
    float ov = g_gates[base + 384 + u];
    float si = 1.f / (1.f + expf(-iv));
    float sf = 1.f / (1.f + expf(-fv));
    float so = 1.f / (1.f + expf(-ov));
    float cn = sf * g_c[d][i][u] + si * tanhf(gv);
    g_c[d][i][u] = cn;
    g_h[d][i][u] = so * tanhf(cn);
}

__global__ void k_hcat() {
    int gid = blockIdx.x * blockDim.x + threadIdx.x;
    if (gid >= NN * HH) return;
    int i = gid >> 7, u = gid & 127;
    int n = g_perm[i];
    g_hcat[(size_t)n * 256 + u] = g_h[0][i][u];
    g_hcat[(size_t)n * 256 + 128 + u] = g_h[1][i][u];
}

// GAT projection GEMMs
__global__ __launch_bounds__(256) void k_gemm_xh1() {
    __shared__ float As[8][132], Bs[8][132];
    int row0 = blockIdx.x * 128;
    if (row0 >= NN) return;
    int col0 = blockIdx.y * 128;
    int tid = threadIdx.x;
    int arow = row0 + (tid >> 1);
    if (arow > NN - 1) arow = NN - 1;
    const float* Aptr = g_hcat + (size_t)arow * 256;
    float acc[8][8];
#pragma unroll
    for (int i = 0; i < 8; i++)
#pragma unroll
        for (int j = 0; j < 8; j++) acc[i][j] = 0.f;
    sgemm_loop(Aptr, g_W1t, 512, col0, 256, tid, acc, As, Bs);
    int ty = tid >> 4, tx = tid & 15;
#pragma unroll
    for (int ii = 0; ii < 8; ii++) {
        int r = row0 + ty * 8 + ii;
        if (r < NN) {
            float* Cp = g_xh1 + (size_t)r * 512 + col0 + tx * 8;
#pragma unroll
            for (int jj = 0; jj < 8; jj++) Cp[jj] = acc[ii][jj];
        }
    }
}

__global__ __launch_bounds__(256) void k_gemm_xh2() {
    __shared__ float As[8][132], Bs[8][132];
    int row0 = blockIdx.x * 128;
    if (row0 >= NN) return;
    int tid = threadIdx.x;
    int arow = row0 + (tid >> 1);
    if (arow > NN - 1) arow = NN - 1;
    const float* Aptr = g_h1 + (size_t)arow * 512;
    float acc[8][8];
#pragma unroll
    for (int i = 0; i < 8; i++)
#pragma unroll
        for (int j = 0; j < 8; j++) acc[i][j] = 0.f;
    sgemm_loop(Aptr, g_W2t, 128, 0, 512, tid, acc, As, Bs);
    int ty = tid >> 4, tx = tid & 15;
#pragma unroll
    for (int ii = 0; ii < 8; ii++) {
        int r = row0 + ty * 8 + ii;
        if (r < NN) {
            float* Cp = g_xh2 + (size_t)r * 128 + tx * 8;
#pragma unroll
            for (int jj = 0; jj < 8; jj++) Cp[jj] = acc[ii][jj];
        }
    }
}

// attention logits
__global__ void k_al1(const float* __restrict__ a1s, const float* __restrict__ a1d) {
    int wid = (blockIdx.x * blockDim.x + threadIdx.x) >> 5;
    int lane = threadIdx.x & 31;
    if (wid >= NN * NHEADS) return;
    int n = wid >> 2, h = wid & 3;
    float s1 = 0.f, s2 = 0.f;
#pragma unroll
    for (int q = 0; q < 4; q++) {
        int f = h * 128 + lane + q * 32;
        float xv = g_xh1[(size_t)n * 512 + f];
        s1 = fmaf(xv, a1s[f], s1);
        s2 = fmaf(xv, a1d[f], s2);
    }
#pragma unroll
    for (int o = 16; o; o >>= 1) {
        s1 += __shfl_xor_sync(0xffffffffu, s1, o);
        s2 += __shfl_xor_sync(0xffffffffu, s2, o);
    }
    if (lane == 0) { g_als1[n * 4 + h] = s1; g_ald1[n * 4 + h] = s2; }
}

__global__ void k_al2(const float* __restrict__ a2s, const float* __restrict__ a2d) {
    int wid = (blockIdx.x * blockDim.x + threadIdx.x) >> 5;
    int lane = threadIdx.x & 31;
    if (wid >= NN) return;
    int n = wid;
    float s1 = 0.f, s2 = 0.f;
#pragma unroll
    for (int q = 0; q < 4; q++) {
        int f = lane + q * 32;
        float xv = g_xh2[(size_t)n * 128 + f];
        s1 = fmaf(xv, a2s[f], s1);
        s2 = fmaf(xv, a2d[f], s2);
    }
#pragma unroll
    for (int o = 16; o; o >>= 1) {
        s1 += __shfl_xor_sync(0xffffffffu, s1, o);
        s2 += __shfl_xor_sync(0xffffffffu, s2, o);
    }
    if (lane == 0) { g_als2[n] = s1; g_ald2[n] = s2; }
}

// ------------------------------------------------------------------
// CSR by destination (edges + self loops)
// ------------------------------------------------------------------
__global__ void k_deg(const int* __restrict__ ei) {
    int i = blockIdx.x * blockDim.x + threadIdx.x;
    if (i < EL) {
        int dst = (i < EE) ? ei[EE + i] : (i - EE);
        atomicAdd(&g_deg[dst], 1);
    }
}

__global__ void k_scan() {
    __shared__ int s[1024];
    const int C = 20;
    int tt = threadIdx.x;
    int begin = tt * C;
    int sum = 0;
    for (int i = 0; i < C; i++) {
        int idx = begin + i;
        if (idx < NN) sum += g_deg[idx];
    }
    s[tt] = sum;
    __syncthreads();
    for (int off = 1; off < 1024; off <<= 1) {
        int v = 0;
        if (tt >= off) v = s[tt - off];
        __syncthreads();
        if (tt >= off) s[tt] += v;
        __syncthreads();
    }
    int excl = s[tt] - sum;
    for (int i = 0; i < C; i++) {
        int idx = begin + i;
        if (idx < NN) { g_rowptr[idx] = excl; excl += g_deg[idx]; }
    }
    if (tt == 1023) g_rowptr[NN] = s[1023];
}

__global__ void k_cursor() {
    int i = blockIdx.x * blockDim.x + threadIdx.x;
    if (i < NN) g_cursor[i] = g_rowptr[i];
}

__global__ void k_scat_e(const int* __restrict__ ei) {
    int i = blockIdx.x * blockDim.x + threadIdx.x;
    if (i < EL) {
        int src = (i < EE) ? ei[i] : (i - EE);
        int dst = (i < EE) ? ei[EE + i] : (i - EE);
        int pos = atomicAdd(&g_cursor[dst], 1);
        g_csrc[pos] = src;
    }
}

// ------------------------------------------------------------------
// GAT aggregation (softmax by dst) — warp per (node, head)
// ------------------------------------------------------------------
__global__ __launch_bounds__(128) void k_gat1_agg(const float* __restrict__ bias1) {
    int n = blockIdx.x;
    int w = threadIdx.x >> 5;   // head
    int lane = threadIdx.x & 31;
    float aldn = g_ald1[n * 4 + w];
    int start = g_rowptr[n], end = g_rowptr[n + 1];
    float emax = -1e30f;
    for (int j = start + lane; j < end; j += 32) {
        int s = g_csrc[j];
        float v = g_als1[s * 4 + w] + aldn;
        v = v > 0.f ? v : 0.2f * v;
        emax = fmaxf(emax, v);
    }
#pragma unroll
    for (int o = 16; o; o >>= 1) emax = fmaxf(emax, __shfl_xor_sync(0xffffffffu, emax, o));
    float denom = 0.f, a0 = 0.f, a1 = 0.f, a2 = 0.f, a3 = 0.f;
    for (int j = start; j < end; j++) {
        int s = g_csrc[j];
        float v = g_als1[s * 4 + w] + aldn;
        v = v > 0.f ? v : 0.2f * v;
        float we = expf(v - emax);
        denom += we;
        const float* xb = g_xh1 + (size_t)s * 512 + w * 128 + lane;
        a0 = fmaf(we, xb[0], a0);
        a1 = fmaf(we, xb[32], a1);
        a2 = fmaf(we, xb[64], a2);
        a3 = fmaf(we, xb[96], a3);
    }
    float inv = 1.f / (denom + 1e-16f);
    int ob = n * 512 + w * 128 + lane;
    int fb = w * 128 + lane;
    g_h1[ob]      = fmaxf(fmaf(a0, inv, 0.f) + bias1[fb], 0.f);
    g_h1[ob + 32] = fmaxf(a1 * inv + bias1[fb + 32], 0.f);
    g_h1[ob + 64] = fmaxf(a2 * inv + bias1[fb + 64], 0.f);
    g_h1[ob + 96] = fmaxf(a3 * inv + bias1[fb + 96], 0.f);
}

__global__ void k_gat2_agg(const float* __restrict__ bias2) {
    int wid = (blockIdx.x * blockDim.x + threadIdx.x) >> 5;
    if (wid >= NN) return;
    int lane = threadIdx.x & 31;
    int n = wid;
    float aldn = g_ald2[n];
    int start = g_rowptr[n], end = g_rowptr[n + 1];
    float emax = -1e30f;
    for (int j = start + lane; j < end; j += 32) {
        int s = g_csrc[j];
        float v = g_als2[s] + aldn;
        v = v > 0.f ? v : 0.2f * v;
        emax = fmaxf(emax, v);
    }
#pragma unroll
    for (int o = 16; o; o >>= 1) emax = fmaxf(emax, __shfl_xor_sync(0xffffffffu, emax, o));
    float denom = 0.f, a0 = 0.f, a1 = 0.f, a2 = 0.f, a3 = 0.f;
    for (int j = start; j < end; j++) {
        int s = g_csrc[j];
        float v = g_als2[s] + aldn;
        v = v > 0.f ? v : 0.2f * v;
        float we = expf(v - emax);
        denom += we;
        const float* xb = g_xh2 + (size_t)s * 128 + lane;
        a0 = fmaf(we, xb[0], a0);
        a1 = fmaf(we, xb[32], a1);
        a2 = fmaf(we, xb[64], a2);
        a3 = fmaf(we, xb[96], a3);
    }
    float inv = 1.f / (denom + 1e-16f);
    int ob = n * 128 + lane;
    g_h2[ob]      = fmaxf(a0 * inv + bias2[lane], 0.f);
    g_h2[ob + 32] = fmaxf(a1 * inv + bias2[lane + 32], 0.f);
    g_h2[ob + 64] = fmaxf(a2 * inv + bias2[lane + 64], 0.f);
    g_h2[ob + 96] = fmaxf(a3 * inv + bias2[lane + 96], 0.f);
}

// final FC — warp per node
__global__ void k_fc(const float* __restrict__ Wfc, const float* __restrict__ bfc,
                     float* __restrict__ out) {
    int wid = (blockIdx.x * blockDim.x + threadIdx.x) >> 5;
    if (wid >= NN) return;
    int lane = threadIdx.x & 31;
    int n = wid;
    float hv[4];
#pragma unroll
    for (int q = 0; q < 4; q++) hv[q] = g_h2[(size_t)n * 128 + lane + 32 * q];
#pragma unroll
    for (int c = 0; c < 10; c++) {
        float p = 0.f;
#pragma unroll
        for (int q = 0; q < 4; q++) p = fmaf(hv[q], Wfc[c * 128 + lane + 32 * q], p);
#pragma unroll
        for (int o = 16; o; o >>= 1) p += __shfl_xor_sync(0xffffffffu, p, o);
        if (lane == 0) out[n * 10 + c] = p + bfc[c];
    }
}

// ------------------------------------------------------------------
extern "C" void kernel_launch(void* const* d_in, const int* in_sizes, int n_in,
                              void* d_out, int out_size) {
    (void)in_sizes; (void)n_in; (void)out_size;
    const float* x        = (const float*)d_in[0];
    const int*   lengths  = (const int*)d_in[1];
    const int*   ei       = (const int*)d_in[2];
    const float* Wih_f    = (const float*)d_in[3];
    const float* Whh_f    = (const float*)d_in[4];
    const float* b_f      = (const float*)d_in[5];
    const float* Wih_b    = (const float*)d_in[6];
    const float* Whh_b    = (const float*)d_in[7];
    const float* b_b      = (const float*)d_in[8];
    const float* W1       = (const float*)d_in[9];
    const float* a1_src   = (const float*)d_in[10];
    const float* a1_dst   = (const float*)d_in[11];
    const float* bias1    = (const float*)d_in[12];
    const float* W2       = (const float*)d_in[13];
    const float* a2_src   = (const float*)d_in[14];
    const float* a2_dst   = (const float*)d_in[15];
    const float* bias2    = (const float*)d_in[16];
    const float* Wfc      = (const float*)d_in[17];
    const float* bfc      = (const float*)d_in[18];
    float* out = (float*)d_out;

    k_zero<<<1024, 256>>>();
    k_prep<<<(459776 + 255) / 256, 256>>>(Wih_f, Whh_f, b_f, Wih_b, Whh_b, b_b, W1, W2);
    k_hist<<<(NN + 255) / 256, 256>>>(lengths);
    k_prepL<<<1, 1>>>();
    k_scatterL<<<(NN + 255) / 256, 256>>>(lengths);
    k_rows<<<(NTT + 255) / 256, 256>>>();

    // CSR build (independent of LSTM)
    k_deg<<<(EL + 255) / 256, 256>>>(ei);
    k_scan<<<1, 1024>>>();
    k_cursor<<<(NN + 255) / 256, 256>>>();
    k_scat_e<<<(EL + 255) / 256, 256>>>(ei);

    // input projection over compacted valid rows
    k_gemm_pre<<<dim3((NTT + 127) / 128, 8), 256>>>(x);

    // recurrence
    for (int t = 0; t < TT; t++) {
        k_gemm_rec<<<dim3((NN + 127) / 128, 8), 256>>>(t);
        k_cell<<<NN, 256>>>(t);
    }
    k_hcat<<<(NN * HH + 255) / 256, 256>>>();

    // GAT layer 1
    k_gemm_xh1<<<dim3((NN + 127) / 128, 4), 256>>>();
    k_al1<<<(NN * NHEADS * 32 + 255) / 256, 256>>>(a1_src, a1_dst);
    k_gat1_agg<<<NN, 128>>>(bias1);

    // GAT layer 2
    k_gemm_xh2<<<dim3((NN + 127) / 128, 1), 256>>>();
    k_al2<<<(NN * 32 + 255) / 256, 256>>>(a2_src, a2_dst);
    k_gat2_agg<<<(NN * 32 + 255) / 256, 256>>>(bias2);

    // FC
    k_fc<<<(NN * 32 + 255) / 256, 256>>>(Wfc, bfc, out);
}

// round 10
// speedup vs baseline: 1.6355x; 1.6265x over previous
#include <cuda_runtime.h>
#include <cuda_bf16.h>
#include <cstdint>

#define NN 20000
#define TT 20
#define FF 128
#define HH 128
#define EE 640000
#define EL (EE + NN)
#define NHEADS 4
#define NTT (NN * TT)

// ------------------------------------------------------------------
// Static device scratch
// ------------------------------------------------------------------
__device__ __align__(256) __nv_bfloat16 g_xh[(size_t)NTT * 128];
__device__ __align__(256) __nv_bfloat16 g_xl[(size_t)NTT * 128];
__device__ __align__(256) __nv_bfloat16 g_Wihh[1024 * 128], g_Wihl[1024 * 128];
__device__ __align__(256) __nv_bfloat16 g_Whhh[2][512][128], g_Whhl[2][512][128];
__device__ __align__(256) __nv_bfloat16 g_W1h[512 * 256], g_W1l[512 * 256];
__device__ __align__(256) __nv_bfloat16 g_W2h[128 * 512], g_W2l[128 * 512];
__device__ __align__(256) __nv_bfloat16 g_hh[2][NN][HH], g_hl[2][NN][HH];
__device__ __align__(256) __nv_bfloat16 g_hcath[(size_t)NN * 256], g_hcatl[(size_t)NN * 256];
__device__ __align__(256) __nv_bfloat16 g_h1h[(size_t)NN * 512], g_h1l[(size_t)NN * 512];
__device__ float g_bih[1024];
__device__ float g_pre[(size_t)NTT * 1024];
__device__ float g_gates[(size_t)NN * 1024];
__device__ float g_h[2][NN][HH];
__device__ float g_c[2][NN][HH];
__device__ float g_xh1[(size_t)NN * 512];
__device__ float g_xh2[(size_t)NN * 128];
__device__ float g_h2[(size_t)NN * 128];
__device__ float g_als1[NN * NHEADS], g_ald1[NN * NHEADS];
__device__ float g_als2[NN], g_ald2[NN];
// length sort
__device__ int g_cnt[21], g_lcur[21], g_active[TT];
__device__ int g_perm[NN], g_lenp[NN];
__device__ int g_nrows;
__device__ int g_rowA[NTT], g_rowC[NTT];
// CSR by dst
__device__ int g_deg[NN], g_rowptr[NN + 1], g_cursor[NN], g_csrc[EL];

__device__ __forceinline__ void split_st(float v, __nv_bfloat16* hi, __nv_bfloat16* lo) {
    __nv_bfloat16 h = __float2bfloat16(v);
    *hi = h;
    *lo = __float2bfloat16(v - __bfloat162float(h));
}

// ------------------------------------------------------------------
// init / prep
// ------------------------------------------------------------------
__global__ void k_zero() {
    int i0 = blockIdx.x * blockDim.x + threadIdx.x;
    int stride = gridDim.x * blockDim.x;
    float* h = &g_h[0][0][0];
    float* c = &g_c[0][0][0];
    const int nh = 2 * NN * HH;
    for (int i = i0; i < nh; i += stride) { h[i] = 0.f; c[i] = 0.f; }
    unsigned int* hb = (unsigned int*)&g_hh[0][0][0];
    unsigned int* lb = (unsigned int*)&g_hl[0][0][0];
    for (int i = i0; i < nh / 2; i += stride) { hb[i] = 0u; lb[i] = 0u; }
    for (int i = i0; i < NN; i += stride) g_deg[i] = 0;
    if (i0 < 21) g_cnt[i0] = 0;
    if (i0 == 0) g_nrows = 0;
}

__global__ void k_prep(const float* __restrict__ Wih_f, const float* __restrict__ Whh_f,
                       const float* __restrict__ b_f,
                       const float* __restrict__ Wih_b, const float* __restrict__ Whh_b,
                       const float* __restrict__ b_b,
                       const float* __restrict__ W1, const float* __restrict__ W2) {
    int idx = blockIdx.x * blockDim.x + threadIdx.x;
    if (idx < 131072) {                        // Wih [1024 j][128 k], j<512 fwd
        int j = idx >> 7, k = idx & 127;
        float v = (j < 512) ? Wih_f[j * FF + k] : Wih_b[(j - 512) * FF + k];
        split_st(v, &g_Wihh[idx], &g_Wihl[idx]);
    } else if (idx < 262144) {                 // Whh [2][512][128]
        int r = idx - 131072;
        int d = r >> 16, rr = r & 65535;
        float v = (d ? Whh_b : Whh_f)[rr];
        split_st(v, &g_Whhh[d][0][0] + rr, &g_Whhl[d][0][0] + rr);
    } else if (idx < 393216) {                 // W1 [512][256]
        int r = idx - 262144;
        split_st(W1[r], &g_W1h[r], &g_W1l[r]);
    } else if (idx < 458752) {                 // W2 [128][512]
        int r = idx - 393216;
        split_st(W2[r], &g_W2h[r], &g_W2l[r]);
    } else if (idx < 459776) {                 // bias
        int j = idx - 458752;
        g_bih[j] = (j < 512) ? b_f[j] : b_b[j - 512];
    }
}

__global__ void k_xconv(const float* __restrict__ x) {
    int idx = blockIdx.x * blockDim.x + threadIdx.x;
    if (idx < NTT * 128) split_st(x[idx], &g_xh[idx], &g_xl[idx]);
}

// ------------------------------------------------------------------
// length counting-sort (descending) + compacted valid-row list
// ------------------------------------------------------------------
__global__ void k_hist(const int* __restrict__ lengths) {
    int n = blockIdx.x * blockDim.x + threadIdx.x;
    if (n < NN) atomicAdd(&g_cnt[lengths[n]], 1);
}
__global__ void k_prepL() {
    int suf = 0;
    for (int l = 20; l >= 0; l--) {
        g_lcur[l] = suf;
        if (l < TT) g_active[l] = suf;
        suf += g_cnt[l];
    }
}
__global__ void k_scatterL(const int* __restrict__ lengths) {
    int n = blockIdx.x * blockDim.x + threadIdx.x;
    if (n < NN) {
        int l = lengths[n];
        int i = atomicAdd(&g_lcur[l], 1);
        g_perm[i] = n;
        g_lenp[i] = l;
    }
}
__global__ void k_rows() {
    int idx = blockIdx.x * blockDim.x + threadIdx.x;
    if (idx < NTT) {
        int i = idx / TT, t = idx % TT;
        if (t < g_lenp[i]) {
            int p = atomicAdd(&g_nrows, 1);
            g_rowA[p] = g_perm[i] * TT + t;
            g_rowC[p] = idx;
        }
    }
}

// ------------------------------------------------------------------
// bf16 split-precision HMMA GEMM: 128x128 CTA tile, 8 warps x (64m x 32n)
// MODE 0: x->pre   1: h->gates   2: hcat->xh1   3: h1->xh2
// ------------------------------------------------------------------
#define MMA(c, a, b) asm volatile( \
    "mma.sync.aligned.m16n8k16.row.col.f32.bf16.bf16.f32 " \
    "{%0,%1,%2,%3},{%4,%5,%6,%7},{%8,%9},{%0,%1,%2,%3};" \
    : "+f"((c)[0]), "+f"((c)[1]), "+f"((c)[2]), "+f"((c)[3]) \
    : "r"((a)[0]), "r"((a)[1]), "r"((a)[2]), "r"((a)[3]), "r"((b)[0]), "r"((b)[1]))

template <int MODE>
__global__ __launch_bounds__(256) void k_mma(int t) {
    __shared__ __align__(16) __nv_bfloat16 sAh[128][40];
    __shared__ __align__(16) __nv_bfloat16 sAl[128][40];
    __shared__ __align__(16) __nv_bfloat16 sBh[128][40];
    __shared__ __align__(16) __nv_bfloat16 sBl[128][40];
    int M, K, jl = 0, d = 0;
    const __nv_bfloat16 *Agh, *Agl, *Bgh, *Bgl;
    int nbase = blockIdx.y * 128;
    if (MODE == 0) {
        M = g_nrows; K = 128;
        Agh = g_xh; Agl = g_xl;
        Bgh = g_Wihh + (size_t)nbase * 128; Bgl = g_Wihl + (size_t)nbase * 128;
    } else if (MODE == 1) {
        M = g_active[t]; K = 128;
        d = blockIdx.y >> 2; jl = (blockIdx.y & 3) * 128;
        Agh = &g_hh[d][0][0]; Agl = &g_hl[d][0][0];
        Bgh = &g_Whhh[d][jl][0]; Bgl = &g_Whhl[d][jl][0];
    } else if (MODE == 2) {
        M = NN; K = 256;
        Agh = g_hcath; Agl = g_hcatl;
        Bgh = g_W1h + (size_t)nbase * 256; Bgl = g_W1l + (size_t)nbase * 256;
    } else {
        M = NN; K = 512;
        Agh = g_h1h; Agl = g_h1l;
        Bgh = g_W2h; Bgl = g_W2l;
    }
    int row0 = blockIdx.x * 128;
    if (row0 >= M) return;
    int tid = threadIdx.x, lane = tid & 31, w = tid >> 5;
    int m0 = (w & 1) * 64, n0 = (w >> 1) * 32;
    int lr = tid >> 1, lk = (tid & 1) * 16;
    int ar = row0 + lr;
    if (ar > M - 1) ar = M - 1;
    size_t aoff = (MODE == 0 ? (size_t)g_rowA[ar] : (size_t)ar) * (size_t)K;
    size_t boff = (size_t)lr * (size_t)K;
    float acc[4][4][4];
#pragma unroll
    for (int a = 0; a < 4; a++)
#pragma unroll
        for (int b = 0; b < 4; b++)
#pragma unroll
            for (int e = 0; e < 4; e++) acc[a][b][e] = 0.f;
    int gr = lane >> 2, q2 = (lane & 3) * 2;
    for (int k0 = 0; k0 < K; k0 += 32) {
        *(uint4*)&sAh[lr][lk]     = *(const uint4*)(Agh + aoff + k0 + lk);
        *(uint4*)&sAh[lr][lk + 8] = *(const uint4*)(Agh + aoff + k0 + lk + 8);
        *(uint4*)&sAl[lr][lk]     = *(const uint4*)(Agl + aoff + k0 + lk);
        *(uint4*)&sAl[lr][lk + 8] = *(const uint4*)(Agl + aoff + k0 + lk + 8);
        *(uint4*)&sBh[lr][lk]     = *(const uint4*)(Bgh + boff + k0 + lk);
        *(uint4*)&sBh[lr][lk + 8] = *(const uint4*)(Bgh + boff + k0 + lk + 8);
        *(uint4*)&sBl[lr][lk]     = *(const uint4*)(Bgl + boff + k0 + lk);
        *(uint4*)&sBl[lr][lk + 8] = *(const uint4*)(Bgl + boff + k0 + lk + 8);
        __syncthreads();
#pragma unroll
        for (int kk = 0; kk < 32; kk += 16) {
            uint32_t ah[4][4], al[4][4], bh[4][2], bl[4][2];
#pragma unroll
            for (int mt = 0; mt < 4; mt++) {
                int r = m0 + mt * 16 + gr;
                ah[mt][0] = *(uint32_t*)&sAh[r][kk + q2];
                ah[mt][1] = *(uint32_t*)&sAh[r + 8][kk + q2];
                ah[mt][2] = *(uint32_t*)&sAh[r][kk + q2 + 8];
                ah[mt][3] = *(uint32_t*)&sAh[r + 8][kk + q2 + 8];
                al[mt][0] = *(uint32_t*)&sAl[r][kk + q2];
                al[mt][1] = *(uint32_t*)&sAl[r + 8][kk + q2];
                al[mt][2] = *(uint32_t*)&sAl[r][kk + q2 + 8];
                al[mt][3] = *(uint32_t*)&sAl[r + 8][kk + q2 + 8];
            }
#pragma unroll
            for (int nt = 0; nt < 4; nt++) {
                int n = n0 + nt * 8 + gr;
                bh[nt][0] = *(uint32_t*)&sBh[n][kk + q2];
                bh[nt][1] = *(uint32_t*)&sBh[n][kk + q2 + 8];
                bl[nt][0] = *(uint32_t*)&sBl[n][kk + q2];
                bl[nt][1] = *(uint32_t*)&sBl[n][kk + q2 + 8];
            }
#pragma unroll
            for (int mt = 0; mt < 4; mt++)
#pragma unroll
                for (int nt = 0; nt < 4; nt++) {
                    MMA(acc[mt][nt], ah[mt], bh[nt]);
                    MMA(acc[mt][nt], ah[mt], bl[nt]);
                    MMA(acc[mt][nt], al[mt], bh[nt]);
                }
        }
        __syncthreads();
    }
    // epilogue
#pragma unroll
    for (int mt = 0; mt < 4; mt++) {
#pragma unroll
        for (int half = 0; half < 2; half++) {
            int r = row0 + m0 + mt * 16 + gr + half * 8;
            if (r >= M) continue;
#pragma unroll
            for (int nt = 0; nt < 4; nt++) {
                float2 v;
                v.x = acc[mt][nt][half * 2];
                v.y = acc[mt][nt][half * 2 + 1];
                int c = n0 + nt * 8 + q2;
                if (MODE == 0) {
                    v.x += g_bih[nbase + c];
                    v.y += g_bih[nbase + c + 1];
                    *(float2*)&g_pre[(size_t)g_rowC[r] * 1024 + nbase + c] = v;
                } else if (MODE == 1) {
                    int prow = d ? r * TT + (g_lenp[r] - 1 - t) : r * TT + t;
                    int j = d * 512 + jl + c;
                    float2 p = *(float2*)&g_pre[(size_t)prow * 1024 + j];
                    v.x += p.x; v.y += p.y;
                    *(float2*)&g_gates[(size_t)r * 1024 + j] = v;
                } else if (MODE == 2) {
                    *(float2*)&g_xh1[(size_t)r * 512 + nbase + c] = v;
                } else {
                    *(float2*)&g_xh2[(size_t)r * 128 + c] = v;
                }
            }
        }
    }
}

__global__ void k_cell(int t) {
    int i = blockIdx.x;
    if (i >= g_active[t]) return;
    int tid = threadIdx.x;
    int d = tid >> 7, u = tid & 127;
    size_t base = (size_t)i * 1024 + d * 512;
    float iv = g_gates[base + u];
    float fv = g_gates[base + 128 + u];
    float gv = g_gates[base + 256 + u];
    float ov = g_gates[base + 384 + u];
    float si = 1.f / (1.f + expf(-iv));
    float sf = 1.f / (1.f + expf(-fv));
    float so = 1.f / (1.f + expf(-ov));
    float cn = sf * g_c[d][i][u] + si * tanhf(gv);
    g_c[d][i][u] = cn;
    float hv = so * tanhf(cn);
    g_h[d][i][u] = hv;
    split_st(hv, &g_hh[d][i][u], &g_hl[d][i][u]);
}

__global__ void k_hcat() {
    int gid = blockIdx.x * blockDim.x + threadIdx.x;
    if (gid >= NN * HH) return;
    int i = gid >> 7, u = gid & 127;
    int n = g_perm[i];
    split_st(g_h[0][i][u], &g_hcath[(size_t)n * 256 + u], &g_hcatl[(size_t)n * 256 + u]);
    split_st(g_h[1][i][u], &g_hcath[(size_t)n * 256 + 128 + u], &g_hcatl[(size_t)n * 256 + 128 + u]);
}

// attention logits
__global__ void k_al1(const float* __restrict__ a1s, const float* __restrict__ a1d) {
    int wid = (blockIdx.x * blockDim.x + threadIdx.x) >> 5;
    int lane = threadIdx.x & 31;
    if (wid >= NN * NHEADS) return;
    int n = wid >> 2, h = wid & 3;
    float s1 = 0.f, s2 = 0.f;
#pragma unroll
    for (int q = 0; q < 4; q++) {
        int f = h * 128 + lane + q * 32;
        float xv = g_xh1[(size_t)n * 512 + f];
        s1 = fmaf(xv, a1s[f], s1);
        s2 = fmaf(xv, a1d[f], s2);
    }
#pragma unroll
    for (int o = 16; o; o >>= 1) {
        s1 += __shfl_xor_sync(0xffffffffu, s1, o);
        s2 += __shfl_xor_sync(0xffffffffu, s2, o);
    }
    if (lane == 0) { g_als1[n * 4 + h] = s1; g_ald1[n * 4 + h] = s2; }
}
__global__ void k_al2(const float* __restrict__ a2s, const float* __restrict__ a2d) {
    int wid = (blockIdx.x * blockDim.x + threadIdx.x) >> 5;
    int lane = threadIdx.x & 31;
    if (wid >= NN) return;
    float s1 = 0.f, s2 = 0.f;
#pragma unroll
    for (int q = 0; q < 4; q++) {
        int f = lane + q * 32;
        float xv = g_xh2[(size_t)wid * 128 + f];
        s1 = fmaf(xv, a2s[f], s1);
        s2 = fmaf(xv, a2d[f], s2);
    }
#pragma unroll
    for (int o = 16; o; o >>= 1) {
        s1 += __shfl_xor_sync(0xffffffffu, s1, o);
        s2 += __shfl_xor_sync(0xffffffffu, s2, o);
    }
    if (lane == 0) { g_als2[wid] = s1; g_ald2[wid] = s2; }
}

// CSR by destination
__global__ void k_deg(const int* __restrict__ ei) {
    int i = blockIdx.x * blockDim.x + threadIdx.x;
    if (i < EL) {
        int dst = (i < EE) ? ei[EE + i] : (i - EE);
        atomicAdd(&g_deg[dst], 1);
    }
}
__global__ void k_scan() {
    __shared__ int s[1024];
    const int C = 20;
    int tt = threadIdx.x;
    int begin = tt * C, sum = 0;
    for (int i = 0; i < C; i++) { int idx = begin + i; if (idx < NN) sum += g_deg[idx]; }
    s[tt] = sum;
    __syncthreads();
    for (int off = 1; off < 1024; off <<= 1) {
        int v = 0;
        if (tt >= off) v = s[tt - off];
        __syncthreads();
        if (tt >= off) s[tt] += v;
        __syncthreads();
    }
    int excl = s[tt] - sum;
    for (int i = 0; i < C; i++) {
        int idx = begin + i;
        if (idx < NN) { g_rowptr[idx] = excl; excl += g_deg[idx]; }
    }
    if (tt == 1023) g_rowptr[NN] = s[1023];
}
__global__ void k_cursor() {
    int i = blockIdx.x * blockDim.x + threadIdx.x;
    if (i < NN) g_cursor[i] = g_rowptr[i];
}
__global__ void k_scat_e(const int* __restrict__ ei) {
    int i = blockIdx.x * blockDim.x + threadIdx.x;
    if (i < EL) {
        int src = (i < EE) ? ei[i] : (i - EE);
        int dst = (i < EE) ? ei[EE + i] : (i - EE);
        int pos = atomicAdd(&g_cursor[dst], 1);
        g_csrc[pos] = src;
    }
}

// GAT aggregation
__global__ __launch_bounds__(128) void k_gat1_agg(const float* __restrict__ bias1) {
    int n = blockIdx.x;
    int w = threadIdx.x >> 5;
    int lane = threadIdx.x & 31;
    float aldn = g_ald1[n * 4 + w];
    int start = g_rowptr[n], end = g_rowptr[n + 1];
    float emax = -1e30f;
    for (int j = start + lane; j < end; j += 32) {
        int s = g_csrc[j];
        float v = g_als1[s * 4 + w] + aldn;
        v = v > 0.f ? v : 0.2f * v;
        emax = fmaxf(emax, v);
    }
#pragma unroll
    for (int o = 16; o; o >>= 1) emax = fmaxf(emax, __shfl_xor_sync(0xffffffffu, emax, o));
    float denom = 0.f, a0 = 0.f, a1 = 0.f, a2 = 0.f, a3 = 0.f;
    for (int j = start; j < end; j++) {
        int s = g_csrc[j];
        float v = g_als1[s * 4 + w] + aldn;
        v = v > 0.f ? v : 0.2f * v;
        float we = expf(v - emax);
        denom += we;
        const float* xb = g_xh1 + (size_t)s * 512 + w * 128 + lane;
        a0 = fmaf(we, xb[0], a0);
        a1 = fmaf(we, xb[32], a1);
        a2 = fmaf(we, xb[64], a2);
        a3 = fmaf(we, xb[96], a3);
    }
    float inv = 1.f / (denom + 1e-16f);
    size_t ob = (size_t)n * 512 + w * 128 + lane;
    int fb = w * 128 + lane;
    float v0 = fmaxf(a0 * inv + bias1[fb], 0.f);
    float v1 = fmaxf(a1 * inv + bias1[fb + 32], 0.f);
    float v2 = fmaxf(a2 * inv + bias1[fb + 64], 0.f);
    float v3 = fmaxf(a3 * inv + bias1[fb + 96], 0.f);
    split_st(v0, &g_h1h[ob], &g_h1l[ob]);
    split_st(v1, &g_h1h[ob + 32], &g_h1l[ob + 32]);
    split_st(v2, &g_h1h[ob + 64], &g_h1l[ob + 64]);
    split_st(v3, &g_h1h[ob + 96], &g_h1l[ob + 96]);
}

__global__ void k_gat2_agg(const float* __restrict__ bias2) {
    int wid = (blockIdx.x * blockDim.x + threadIdx.x) >> 5;
    if (wid >= NN) return;
    int lane = threadIdx.x & 31;
    int n = wid;
    float aldn = g_ald2[n];
    int start = g_rowptr[n], end = g_rowptr[n + 1];
    float emax = -1e30f;
    for (int j = start + lane; j < end; j += 32) {
        int s = g_csrc[j];
        float v = g_als2[s] + aldn;
        v = v > 0.f ? v : 0.2f * v;
        emax = fmaxf(emax, v);
    }
#pragma unroll
    for (int o = 16; o; o >>= 1) emax = fmaxf(emax, __shfl_xor_sync(0xffffffffu, emax, o));
    float denom = 0.f, a0 = 0.f, a1 = 0.f, a2 = 0.f, a3 = 0.f;
    for (int j = start; j < end; j++) {
        int s = g_csrc[j];
        float v = g_als2[s] + aldn;
        v = v > 0.f ? v : 0.2f * v;
        float we = expf(v - emax);
        denom += we;
        const float* xb = g_xh2 + (size_t)s * 128 + lane;
        a0 = fmaf(we, xb[0], a0);
        a1 = fmaf(we, xb[32], a1);
        a2 = fmaf(we, xb[64], a2);
        a3 = fmaf(we, xb[96], a3);
    }
    float inv = 1.f / (denom + 1e-16f);
    int ob = n * 128 + lane;
    g_h2[ob]      = fmaxf(a0 * inv + bias2[lane], 0.f);
    g_h2[ob + 32] = fmaxf(a1 * inv + bias2[lane + 32], 0.f);
    g_h2[ob + 64] = fmaxf(a2 * inv + bias2[lane + 64], 0.f);
    g_h2[ob + 96] = fmaxf(a3 * inv + bias2[lane + 96], 0.f);
}

// final FC — warp per node
__global__ void k_fc(const float* __restrict__ Wfc, const float* __restrict__ bfc,
                     float* __restrict__ out) {
    int wid = (blockIdx.x * blockDim.x + threadIdx.x) >> 5;
    if (wid >= NN) return;
    int lane = threadIdx.x & 31;
    int n = wid;
    float hv[4];
#pragma unroll
    for (int q = 0; q < 4; q++) hv[q] = g_h2[(size_t)n * 128 + lane + 32 * q];
#pragma unroll
    for (int c = 0; c < 10; c++) {
        float p = 0.f;
#pragma unroll
        for (int q = 0; q < 4; q++) p = fmaf(hv[q], Wfc[c * 128 + lane + 32 * q], p);
#pragma unroll
        for (int o = 16; o; o >>= 1) p += __shfl_xor_sync(0xffffffffu, p, o);
        if (lane == 0) out[n * 10 + c] = p + bfc[c];
    }
}

// ------------------------------------------------------------------
extern "C" void kernel_launch(void* const* d_in, const int* in_sizes, int n_in,
                              void* d_out, int out_size) {
    (void)in_sizes; (void)n_in; (void)out_size;
    const float* x       = (const float*)d_in[0];
    const int*   lengths = (const int*)d_in[1];
    const int*   ei      = (const int*)d_in[2];
    const float* Wih_f   = (const float*)d_in[3];
    const float* Whh_f   = (const float*)d_in[4];
    const float* b_f     = (const float*)d_in[5];
    const float* Wih_b   = (const float*)d_in[6];
    const float* Whh_b   = (const float*)d_in[7];
    const float* b_b     = (const float*)d_in[8];
    const float* W1      = (const float*)d_in[9];
    const float* a1_src  = (const float*)d_in[10];
    const float* a1_dst  = (const float*)d_in[11];
    const float* bias1   = (const float*)d_in[12];
    const float* W2      = (const float*)d_in[13];
    const float* a2_src  = (const float*)d_in[14];
    const float* a2_dst  = (const float*)d_in[15];
    const float* bias2   = (const float*)d_in[16];
    const float* Wfc     = (const float*)d_in[17];
    const float* bfc     = (const float*)d_in[18];
    float* out = (float*)d_out;

    k_zero<<<1024, 256>>>();
    k_prep<<<(459776 + 255) / 256, 256>>>(Wih_f, Whh_f, b_f, Wih_b, Whh_b, b_b, W1, W2);
    k_xconv<<<(NTT * 128 + 255) / 256, 256>>>(x);
    k_hist<<<(NN + 255) / 256, 256>>>(lengths);
    k_prepL<<<1, 1>>>();
    k_scatterL<<<(NN + 255) / 256, 256>>>(lengths);
    k_rows<<<(NTT + 255) / 256, 256>>>();

    // CSR build (independent of LSTM)
    k_deg<<<(EL + 255) / 256, 256>>>(ei);
    k_scan<<<1, 1024>>>();
    k_cursor<<<(NN + 255) / 256, 256>>>();
    k_scat_e<<<(EL + 255) / 256, 256>>>(ei);

    // input projection over compacted valid rows
    k_mma<0><<<dim3((NTT + 127) / 128, 8), 256>>>(0);

    // recurrence
    for (int t = 0; t < TT; t++) {
        k_mma<1><<<dim3((NN + 127) / 128, 8), 256>>>(t);
        k_cell<<<NN, 256>>>(t);
    }
    k_hcat<<<(NN * HH + 255) / 256, 256>>>();

    // GAT layer 1
    k_mma<2><<<dim3((NN + 127) / 128, 4), 256>>>(0);
    k_al1<<<(NN * NHEADS * 32 + 255) / 256, 256>>>(a1_src, a1_dst);
    k_gat1_agg<<<NN, 128>>>(bias1);

    // GAT layer 2
    k_mma<3><<<dim3((NN + 127) / 128, 1), 256>>>(0);
    k_al2<<<(NN * 32 + 255) / 256, 256>>>(a2_src, a2_dst);
    k_gat2_agg<<<(NN * 32 + 255) / 256, 256>>>(bias2);

    // FC
    k_fc<<<(NN * 32 + 255) / 256, 256>>>(Wfc, bfc, out);
}